// round 11
// baseline (speedup 1.0000x reference)
#include <cuda_runtime.h>
#include <cuda_fp16.h>
#include <math.h>
#include <stdint.h>

// ---------------------------------------------------------------------------
// BailingMoeV2Gate (plain sm_103 target, no tcgen05):
// logits = X[T,4096] @ W[256,4096]^T via mma.sync.m16n8k16 fp16 2-way split,
// 3 products {x0w0, x0w1, x1w0}. W pre-scaled by 2^12, X by 2^4; epilogue
// x 2^-16. One 6-mma chain per stage (C=0 seeded) + Kahan RN master accum.
// Tile M=32 x N=256 (full expert dim): A read/split ONCE per band, W from L2.
// 512 CTAs at occupancy 2 -> work-stealing smooths the wave quantization.
// Per-output accumulation order bit-identical to the R9 passing kernel.
// Output (fp32 concat): [T*8] idx, [T*8] weights, [T*256] logits.
// ---------------------------------------------------------------------------

#define HID   4096
#define NEXP  256
#define KC    32
#define NST   (HID / KC)   // 128 stages

__device__ float g_logits_scratch[16384 * 256];
__device__ __half g_W0[NEXP * HID];   // fp16(W * 4096)
__device__ __half g_W1[NEXP * HID];   // fp16 residual

__device__ __forceinline__ uint32_t smem_u32(const void* p) {
    uint32_t a;
    asm("{ .reg .u64 t; cvta.to.shared.u64 t, %1; cvt.u32.u64 %0, t; }"
        : "=r"(a) : "l"(p));
    return a;
}

#define MMA_INIT(d, a, b)                                                  \
    asm volatile(                                                          \
        "mma.sync.aligned.m16n8k16.row.col.f32.f16.f16.f32 "               \
        "{%0,%1,%2,%3}, {%4,%5,%6,%7}, {%8,%9}, {%10,%11,%12,%13};"        \
        : "=f"((d)[0]), "=f"((d)[1]), "=f"((d)[2]), "=f"((d)[3])           \
        : "r"((a)[0]), "r"((a)[1]), "r"((a)[2]), "r"((a)[3]),              \
          "r"((b)[0]), "r"((b)[1]),                                        \
          "f"(0.0f), "f"(0.0f), "f"(0.0f), "f"(0.0f))

#define MMA_ACC(d, a, b)                                                   \
    asm volatile(                                                          \
        "mma.sync.aligned.m16n8k16.row.col.f32.f16.f16.f32 "               \
        "{%0,%1,%2,%3}, {%4,%5,%6,%7}, {%8,%9}, {%0,%1,%2,%3};"            \
        : "+f"((d)[0]), "+f"((d)[1]), "+f"((d)[2]), "+f"((d)[3])           \
        : "r"((a)[0]), "r"((a)[1]), "r"((a)[2]), "r"((a)[3]),              \
          "r"((b)[0]), "r"((b)[1]))

#define LDMATRIX_X4(r, addr)                                               \
    asm volatile("ldmatrix.sync.aligned.m8n8.x4.shared.b16 "               \
                 "{%0,%1,%2,%3}, [%4];"                                    \
                 : "=r"((r)[0]), "=r"((r)[1]), "=r"((r)[2]), "=r"((r)[3])  \
                 : "r"(addr))

#define LDMATRIX_X2(r, addr)                                               \
    asm volatile("ldmatrix.sync.aligned.m8n8.x2.shared.b16 {%0,%1}, [%2];" \
                 : "=r"((r)[0]), "=r"((r)[1]) : "r"(addr))

#define CP_ASYNC16(dst, src)                                               \
    asm volatile("{ .reg .u64 g; cvta.to.global.u64 g, %1; "               \
                 "cp.async.ca.shared.global [%0], [g], 16; }"              \
                 :: "r"(dst), "l"(src))

// ====================== W split pre-kernel =================================
__global__ __launch_bounds__(256) void wsplit_kernel(const float* __restrict__ W) {
    size_t i = ((size_t)blockIdx.x * 256 + threadIdx.x) * 4;
    float4 v = *(const float4*)(W + i);
    float a[4] = {v.x, v.y, v.z, v.w};
#pragma unroll
    for (int j = 0; j < 4; j++) {
        float x = a[j] * 4096.0f;
        __half w0 = __float2half_rn(x);
        float r1 = x - __half2float(w0);
        __half w1 = __float2half_rn(r1);
        g_W0[i + j] = w0;
        g_W1[i + j] = w1;
    }
}

// ====================== split-fp16 mma.sync GEMM ===========================
// Grid: T/32 = 512 CTAs. CTA tile M=32, N=256. 256 threads = 8 warps
// (2M x 4N), warp tile 16x64. KC=32 (2 k16 steps), 2-stage double buffer.
// SMEM fp16 tiles, 80B padded row stride (64B data + 16B pad).
#define A_ROW    80
#define A_SPLIT  (32 * A_ROW)        // 2560  (one split tile)
#define A_STG    (2 * A_SPLIT)       // 5120  (both splits, one buffer)
#define B_OFF    (2 * A_STG)         // 10240
#define B_SPLIT  (256 * A_ROW)       // 20480
#define B_STG    (2 * B_SPLIT)       // 40960
#define GEMM_SMEM (B_OFF + 2 * B_STG)  // 92160

__global__ void __launch_bounds__(256, 2) gemm_fp16_split(
    const float* __restrict__ X, float* __restrict__ C)
{
    extern __shared__ char smem[];
    const uint32_t sb = smem_u32(smem);
    const int tid  = threadIdx.x;
    const int lane = tid & 31;
    const int wid  = tid >> 5;
    const int wm   = wid >> 2;      // 0..1 (M)
    const int wn   = wid & 3;       // 0..3 (N)
    const int bm   = blockIdx.x * 32;

    // ---- A loader: 256 threads, 4 floats each ----
    const int ar = tid >> 3;         // row 0..31
    const int aq = tid & 7;          // 4-float chunk within 32
    const float* aptr = X + (size_t)(bm + ar) * HID + aq * 4;

    // ---- B loader: 8 cp.async 16B chunks per thread per stage ----
    // j = tid*8+c in [0,2048): p = j>>10, row = (j&1023)>>2, ch = j&3
    const __half* wbase[2] = {g_W0, g_W1};

    float acc[8][4], cmp[8][4];
#pragma unroll
    for (int n = 0; n < 8; n++)
#pragma unroll
        for (int k = 0; k < 4; k++) { acc[n][k] = 0.0f; cmp[n][k] = 0.0f; }

    float4 xs;   // 4 staged fp32

    auto a_ldg = [&](int s) {
        xs = *(const float4*)(aptr + s * KC);
    };
    auto b_cpasync = [&](int s, int b) {
#pragma unroll
        for (int c = 0; c < 8; c++) {
            int j   = tid * 8 + c;
            int p   = j >> 10;
            int rem = j & 1023;
            int row = rem >> 2;
            int ch  = rem & 3;
            const char* src = (const char*)(wbase[p] + (size_t)row * HID + s * KC) + ch * 16;
            uint32_t dst = sb + B_OFF + b * B_STG + p * B_SPLIT + row * A_ROW + ch * 16;
            CP_ASYNC16(dst, src);
        }
        asm volatile("cp.async.commit_group;" ::: "memory");
    };
    auto a_sts = [&](int b) {
        float xv[4] = {xs.x, xs.y, xs.z, xs.w};
        __half2 h0[2], h1[2];
#pragma unroll
        for (int i = 0; i < 2; i++) {
            float xa = xv[2 * i] * 16.0f;       // exact scale
            float xb = xv[2 * i + 1] * 16.0f;
            __half a0 = __float2half_rn(xa);
            float ra = xa - __half2float(a0);
            __half a1 = __float2half_rn(ra);
            __half b0 = __float2half_rn(xb);
            float rb = xb - __half2float(b0);
            __half b1 = __float2half_rn(rb);
            h0[i] = __half2(a0, b0);
            h1[i] = __half2(a1, b1);
        }
        char* base = smem + b * A_STG + ar * A_ROW + aq * 8;
        *(uint2*)(base)           = *(const uint2*)h0;
        *(uint2*)(base + A_SPLIT) = *(const uint2*)h1;
    };

    // ---- ldmatrix addresses ----
    // A x4: matrix mt = lane>>3: rows (lane&7)+8*(mt&1), k-half = mt>>1
    const int a_mt = lane >> 3;
    const uint32_t a_addr0 = sb + (wm * 16 + (lane & 7) + ((a_mt & 1) << 3)) * A_ROW
                           + (a_mt >> 1) * 16;
    // B x2: lanes 0-15: rows n = (l15&7), k-half = (l15>>3)*16
    const int l15 = lane & 15;
    const uint32_t b_addr0 = sb + B_OFF + (wn * 64 + (l15 & 7)) * A_ROW
                           + (l15 >> 3) * 16;

    auto compute = [&](int b) {
        uint32_t af[2][2][4];   // [split][kk][frag]
#pragma unroll
        for (int p = 0; p < 2; p++)
#pragma unroll
            for (int kk = 0; kk < 2; kk++)
                LDMATRIX_X4(af[p][kk],
                    a_addr0 + b * A_STG + p * A_SPLIT + kk * 32);
#pragma unroll
        for (int nt = 0; nt < 8; nt++) {
            uint32_t bf[2][2][2];  // [split][kk][frag]
#pragma unroll
            for (int p = 0; p < 2; p++)
#pragma unroll
                for (int kk = 0; kk < 2; kk++)
                    LDMATRIX_X2(bf[p][kk],
                        b_addr0 + b * B_STG + p * B_SPLIT + nt * 8 * A_ROW + kk * 32);
            float ch[4];       // one 6-mma chain per stage (C=0 seeded)
            MMA_INIT(ch, af[0][0], bf[0][0]);   // x0*w0 kk0
            MMA_ACC (ch, af[0][0], bf[1][0]);   // x0*w1 kk0
            MMA_ACC (ch, af[1][0], bf[0][0]);   // x1*w0 kk0
            MMA_ACC (ch, af[0][1], bf[0][1]);   // x0*w0 kk1
            MMA_ACC (ch, af[0][1], bf[1][1]);   // x0*w1 kk1
            MMA_ACC (ch, af[1][1], bf[0][1]);   // x1*w0 kk1
#pragma unroll
            for (int k = 0; k < 4; k++) {       // Kahan master add (RN)
                float y = __fadd_rn(ch[k], -cmp[nt][k]);
                float t = __fadd_rn(acc[nt][k], y);
                cmp[nt][k] = __fadd_rn(__fadd_rn(t, -acc[nt][k]), -y);
                acc[nt][k] = t;
            }
        }
    };

    // ---- prologue ----
    a_ldg(0);
    b_cpasync(0, 0);
    a_sts(0);
    asm volatile("cp.async.wait_group 0;" ::: "memory");
    __syncthreads();

    // ---- mainloop ----
    for (int s = 0; s < NST; s++) {
        const int b = s & 1;
        const bool more = (s + 1 < NST);
        if (more) {
            a_ldg(s + 1);
            b_cpasync(s + 1, b ^ 1);
        }
        compute(b);
        if (more) a_sts(b ^ 1);
        asm volatile("cp.async.wait_group 0;" ::: "memory");
        __syncthreads();
    }

    // ---- epilogue: undo 2^16 scaling (exact) ----
    const float SC = 1.0f / 65536.0f;
#pragma unroll
    for (int nt = 0; nt < 8; nt++) {
        const int row = bm + wm * 16 + (lane >> 2);
        const int col = wn * 64 + nt * 8 + ((lane & 3) << 1);
        float* cp = C + (size_t)row * NEXP + col;
        *(float2*)cp = make_float2(acc[nt][0] * SC, acc[nt][1] * SC);
        *(float2*)(cp + 8 * NEXP) = make_float2(acc[nt][2] * SC, acc[nt][3] * SC);
    }
}

// ======================== routing: one warp per token =======================
__global__ __launch_bounds__(256) void routing_kernel(
    const float* __restrict__ logits, const float* __restrict__ bias,
    float* __restrict__ out_idx, float* __restrict__ out_w, int T)
{
    const int wip  = threadIdx.x >> 5;
    const int lane = threadIdx.x & 31;
    const int t = blockIdx.x * 8 + wip;
    if (t >= T) return;

    __shared__ float s_sc[8][256];
    __shared__ float s_sr[8][256];
    __shared__ float s_gv[8][8];
    __shared__ int   s_gi[8][8];

    float* sc = s_sc[wip];
    float* sr = s_sr[wip];
    const float* lrow = logits + (size_t)t * 256;

#pragma unroll
    for (int i = 0; i < 8; i++) {
        int e = i * 32 + lane;
        float l = lrow[e];
        float s = 1.0f / (1.0f + expf(-l));
        sc[e] = s;
        sr[e] = s + bias[e];
    }
    __syncwarp();

    float gscore = -INFINITY;
    if (lane < 8) {
        float m1 = -INFINITY, m2 = -INFINITY;
#pragma unroll
        for (int j = 0; j < 32; j++) {
            float v = sr[lane * 32 + ((j + lane * 4) & 31)];
            if (v > m1) { m2 = m1; m1 = v; }
            else if (v > m2) { m2 = v; }
        }
        gscore = m1 + m2;
    }

    float gs[8];
#pragma unroll
    for (int g = 0; g < 8; g++) gs[g] = __shfl_sync(0xffffffffu, gscore, g);
    unsigned gmask = 0;
#pragma unroll
    for (int k = 0; k < 4; k++) {
        int bi = -1; float bv = -INFINITY;
#pragma unroll
        for (int g = 0; g < 8; g++) {
            bool taken = (gmask >> g) & 1u;
            if (!taken && gs[g] > bv) { bv = gs[g]; bi = g; }
        }
        gmask |= 1u << bi;
    }

    float vals[8];
#pragma unroll
    for (int i = 0; i < 8; i++)
        vals[i] = ((gmask >> i) & 1u) ? sr[i * 32 + lane] : -INFINITY;

    float sum = 0.0f;
    for (int k = 0; k < 8; k++) {
        float bv = -INFINITY; int bi = 0x7fffffff;
#pragma unroll
        for (int i = 0; i < 8; i++) {
            int e = i * 32 + lane;
            if (vals[i] > bv || (vals[i] == bv && e < bi)) { bv = vals[i]; bi = e; }
        }
#pragma unroll
        for (int off = 16; off; off >>= 1) {
            float ov = __shfl_xor_sync(0xffffffffu, bv, off);
            int   oi = __shfl_xor_sync(0xffffffffu, bi, off);
            if (ov > bv || (ov == bv && oi < bi)) { bv = ov; bi = oi; }
        }
        if ((bi & 31) == lane) vals[bi >> 5] = -INFINITY;
        float g = sc[bi];
        sum += g;
        if (lane == 0) { s_gv[wip][k] = g; s_gi[wip][k] = bi; }
    }
    __syncwarp();

    if (lane < 8) {
        float w = s_gv[wip][lane] / (sum + 1e-20f) * 2.5f;
        out_w[(size_t)t * 8 + lane]   = w;
        out_idx[(size_t)t * 8 + lane] = (float)s_gi[wip][lane];
    }
}

// ============================== launch ======================================
extern "C" void kernel_launch(void* const* d_in, const int* in_sizes, int n_in,
                              void* d_out, int out_size)
{
    const float* X    = (const float*)d_in[0];  // [T, H]
    const float* W    = (const float*)d_in[1];  // [E, H]
    const float* bias = (const float*)d_in[2];  // [E]

    const int E = in_sizes[2];
    const int H = in_sizes[1] / E;
    const int T = in_sizes[0] / H;

    float* out     = (float*)d_out;
    float* out_idx = out;
    float* out_w   = out + (size_t)T * 8;

    float* logits;
    if ((size_t)out_size >= (size_t)T * 16 + (size_t)T * E) {
        logits = out + (size_t)T * 16;
    } else {
        float* p;
        cudaGetSymbolAddress((void**)&p, g_logits_scratch);
        logits = p;
    }

    // 1) W -> two fp16 split arrays (scaled by 2^12)
    wsplit_kernel<<<(E * H / 4 + 255) / 256, 256>>>(W);

    // 2) tensor-core split GEMM -> logits (M=32 x N=256 tiles, occ 2)
    cudaFuncSetAttribute(gemm_fp16_split,
                         cudaFuncAttributeMaxDynamicSharedMemorySize, GEMM_SMEM);
    gemm_fp16_split<<<T / 32, 256, GEMM_SMEM>>>(X, logits);

    // 3) routing
    routing_kernel<<<(T + 7) / 8, 256>>>(logits, bias, out_idx, out_w, T);
}

// round 12
// speedup vs baseline: 1.4047x; 1.4047x over previous
#include <cuda_runtime.h>
#include <cuda_fp16.h>
#include <math.h>
#include <stdint.h>

// ---------------------------------------------------------------------------
// BailingMoeV2Gate (plain sm_103 target, no tcgen05):
// logits = X[T,4096] @ W[256,4096]^T via mma.sync.m16n8k16 fp16 2-way split,
// 3 products {x0w0, x0w1, x1w0}. W pre-scaled by 2^12, X by 2^4; epilogue
// x 2^-16. Per 32-k block: one 6-mma chain (C=0 seeded) + Kahan RN master
// add -- global accumulation order bit-identical to the R9 passing kernel.
// Tile M=128 x N=128 (R9 shape), KC=64 -> 64 stages (halved stage overhead).
// Output (fp32 concat): [T*8] idx, [T*8] weights, [T*256] logits.
// ---------------------------------------------------------------------------

#define HID   4096
#define NEXP  256
#define KC    64
#define NST   (HID / KC)   // 64 stages

__device__ float g_logits_scratch[16384 * 256];
__device__ __half g_W0[NEXP * HID];   // fp16(W * 4096)
__device__ __half g_W1[NEXP * HID];   // fp16 residual

__device__ __forceinline__ uint32_t smem_u32(const void* p) {
    uint32_t a;
    asm("{ .reg .u64 t; cvta.to.shared.u64 t, %1; cvt.u32.u64 %0, t; }"
        : "=r"(a) : "l"(p));
    return a;
}

#define MMA_INIT(d, a, b)                                                  \
    asm volatile(                                                          \
        "mma.sync.aligned.m16n8k16.row.col.f32.f16.f16.f32 "               \
        "{%0,%1,%2,%3}, {%4,%5,%6,%7}, {%8,%9}, {%10,%11,%12,%13};"        \
        : "=f"((d)[0]), "=f"((d)[1]), "=f"((d)[2]), "=f"((d)[3])           \
        : "r"((a)[0]), "r"((a)[1]), "r"((a)[2]), "r"((a)[3]),              \
          "r"((b)[0]), "r"((b)[1]),                                        \
          "f"(0.0f), "f"(0.0f), "f"(0.0f), "f"(0.0f))

#define MMA_ACC(d, a, b)                                                   \
    asm volatile(                                                          \
        "mma.sync.aligned.m16n8k16.row.col.f32.f16.f16.f32 "               \
        "{%0,%1,%2,%3}, {%4,%5,%6,%7}, {%8,%9}, {%0,%1,%2,%3};"            \
        : "+f"((d)[0]), "+f"((d)[1]), "+f"((d)[2]), "+f"((d)[3])           \
        : "r"((a)[0]), "r"((a)[1]), "r"((a)[2]), "r"((a)[3]),              \
          "r"((b)[0]), "r"((b)[1]))

#define LDMATRIX_X4(r, addr)                                               \
    asm volatile("ldmatrix.sync.aligned.m8n8.x4.shared.b16 "               \
                 "{%0,%1,%2,%3}, [%4];"                                    \
                 : "=r"((r)[0]), "=r"((r)[1]), "=r"((r)[2]), "=r"((r)[3])  \
                 : "r"(addr))

#define LDMATRIX_X2(r, addr)                                               \
    asm volatile("ldmatrix.sync.aligned.m8n8.x2.shared.b16 {%0,%1}, [%2];" \
                 : "=r"((r)[0]), "=r"((r)[1]) : "r"(addr))

#define CP_ASYNC16(dst, src)                                               \
    asm volatile("{ .reg .u64 g; cvta.to.global.u64 g, %1; "               \
                 "cp.async.ca.shared.global [%0], [g], 16; }"              \
                 :: "r"(dst), "l"(src))

// ====================== W split pre-kernel =================================
__global__ __launch_bounds__(256) void wsplit_kernel(const float* __restrict__ W) {
    size_t i = ((size_t)blockIdx.x * 256 + threadIdx.x) * 4;
    float4 v = *(const float4*)(W + i);
    float a[4] = {v.x, v.y, v.z, v.w};
#pragma unroll
    for (int j = 0; j < 4; j++) {
        float x = a[j] * 4096.0f;
        __half w0 = __float2half_rn(x);
        float r1 = x - __half2float(w0);
        __half w1 = __float2half_rn(r1);
        g_W0[i + j] = w0;
        g_W1[i + j] = w1;
    }
}

// ====================== split-fp16 mma.sync GEMM ===========================
// Grid (2, T/128): CTA tile M=128, N=128. 256 threads = 8 warps (4M x 2N),
// warp tile 32x64. KC=64 per stage (4 k16 steps), 2-stage double buffer.
// SMEM fp16 tiles, 144B padded row stride (128B data + 16B pad).
#define A_ROW    144
#define A_SPLIT  (128 * A_ROW)       // 18432
#define A_BUF    (2 * A_SPLIT)       // 36864 (2 splits, one stage buffer)
#define B_OFF    (2 * A_BUF)         // 73728
#define B_SPLIT  (128 * A_ROW)
#define B_BUF    (2 * B_SPLIT)
#define GEMM_SMEM (B_OFF + 2 * B_BUF)  // 147456

__global__ void __launch_bounds__(256, 1) gemm_fp16_split(
    const float* __restrict__ X, float* __restrict__ C)
{
    extern __shared__ char smem[];
    const uint32_t sb = smem_u32(smem);
    const int tid  = threadIdx.x;
    const int lane = tid & 31;
    const int wid  = tid >> 5;
    const int wm   = wid >> 1;      // 0..3 (M)
    const int wn   = wid & 1;       // 0..1 (N)
    const int bm   = blockIdx.y * 128;
    const int bn   = blockIdx.x * 128;

    // ---- A loader: 256 threads, 32 floats each: row = tid>>1, half = tid&1
    const int ar  = tid >> 1;
    const int akh = tid & 1;
    const float* aptr = X + (size_t)(bm + ar) * HID + akh * 32;

    // ---- B loader: 8 cp.async 16B chunks per thread per stage ----
    // j = tid*8+c in [0,2048): p = j>>10, row = (j&1023)>>3, ch = j&7
    const __half* wbase[2] = {g_W0, g_W1};

    float acc[2][8][4], cmp[2][8][4];
#pragma unroll
    for (int m = 0; m < 2; m++)
#pragma unroll
        for (int n = 0; n < 8; n++)
#pragma unroll
            for (int k = 0; k < 4; k++) { acc[m][n][k] = 0.0f; cmp[m][n][k] = 0.0f; }

    float4 xsv[8];   // 32 staged fp32

    auto a_ldg = [&](int s) {
        const float* p = aptr + s * KC;
#pragma unroll
        for (int j = 0; j < 8; j++) xsv[j] = *(const float4*)(p + j * 4);
    };
    auto b_cpasync = [&](int s, int b) {
#pragma unroll
        for (int c = 0; c < 8; c++) {
            int j   = tid * 8 + c;
            int p   = j >> 10;
            int rem = j & 1023;
            int row = rem >> 3;
            int ch  = rem & 7;
            const char* src = (const char*)(wbase[p] + (size_t)(bn + row) * HID + s * KC) + ch * 16;
            uint32_t dst = sb + B_OFF + b * B_BUF + p * B_SPLIT + row * A_ROW + ch * 16;
            CP_ASYNC16(dst, src);
        }
        asm volatile("cp.async.commit_group;" ::: "memory");
    };
    auto a_sts = [&](int b) {
        const float* xv = (const float*)xsv;
        __half2 h0[16], h1[16];
#pragma unroll
        for (int i = 0; i < 16; i++) {
            float xa = xv[2 * i] * 16.0f;       // exact scale
            float xb = xv[2 * i + 1] * 16.0f;
            __half a0 = __float2half_rn(xa);
            float ra = xa - __half2float(a0);
            __half a1 = __float2half_rn(ra);
            __half b0 = __float2half_rn(xb);
            float rb = xb - __half2float(b0);
            __half b1 = __float2half_rn(rb);
            h0[i] = __half2(a0, b0);
            h1[i] = __half2(a1, b1);
        }
        char* base = smem + b * A_BUF + ar * A_ROW + akh * 64;
#pragma unroll
        for (int j = 0; j < 4; j++) {
            *(uint4*)(base + j * 16)           = ((const uint4*)h0)[j];
            *(uint4*)(base + A_SPLIT + j * 16) = ((const uint4*)h1)[j];
        }
    };

    // ---- ldmatrix addresses ----
    // A x4: matrix mt = lane>>3: rows (lane&7)+8*(mt&1), k-half = mt>>1
    const int a_mt = lane >> 3;
    const uint32_t a_addr0 = sb + (wm * 32 + (lane & 7) + ((a_mt & 1) << 3)) * A_ROW
                           + (a_mt >> 1) * 16;
    // B x2: lanes 0-15: rows n = (l15&7), k-half = (l15>>3)*16
    const int l15 = lane & 15;
    const uint32_t b_addr0 = sb + B_OFF + (wn * 64 + (l15 & 7)) * A_ROW
                           + (l15 >> 3) * 16;

    auto compute = [&](int b) {
#pragma unroll
        for (int blk = 0; blk < 2; blk++) {          // two 32-k blocks
            uint32_t af[2][2][2][4];   // [split][m][kkin][frag]
#pragma unroll
            for (int p = 0; p < 2; p++)
#pragma unroll
                for (int m = 0; m < 2; m++)
#pragma unroll
                    for (int kki = 0; kki < 2; kki++)
                        LDMATRIX_X4(af[p][m][kki],
                            a_addr0 + b * A_BUF + p * A_SPLIT + m * 16 * A_ROW
                            + (blk * 2 + kki) * 32);
#pragma unroll
            for (int nt = 0; nt < 8; nt++) {
                uint32_t bf[2][2][2];  // [split][kkin][frag]
#pragma unroll
                for (int p = 0; p < 2; p++)
#pragma unroll
                    for (int kki = 0; kki < 2; kki++)
                        LDMATRIX_X2(bf[p][kki],
                            b_addr0 + b * B_BUF + p * B_SPLIT + nt * 8 * A_ROW
                            + (blk * 2 + kki) * 32);
#pragma unroll
                for (int m = 0; m < 2; m++) {
                    float ch[4];       // one 6-mma chain per 32-k block
                    MMA_INIT(ch, af[0][m][0], bf[0][0]);   // x0*w0 kk0
                    MMA_ACC (ch, af[0][m][0], bf[1][0]);   // x0*w1 kk0
                    MMA_ACC (ch, af[1][m][0], bf[0][0]);   // x1*w0 kk0
                    MMA_ACC (ch, af[0][m][1], bf[0][1]);   // x0*w0 kk1
                    MMA_ACC (ch, af[0][m][1], bf[1][1]);   // x0*w1 kk1
                    MMA_ACC (ch, af[1][m][1], bf[0][1]);   // x1*w0 kk1
#pragma unroll
                    for (int k = 0; k < 4; k++) {          // Kahan master add
                        float y = __fadd_rn(ch[k], -cmp[m][nt][k]);
                        float t = __fadd_rn(acc[m][nt][k], y);
                        cmp[m][nt][k] = __fadd_rn(__fadd_rn(t, -acc[m][nt][k]), -y);
                        acc[m][nt][k] = t;
                    }
                }
            }
        }
    };

    // ---- prologue ----
    a_ldg(0);
    b_cpasync(0, 0);
    a_sts(0);
    asm volatile("cp.async.wait_group 0;" ::: "memory");
    __syncthreads();

    // ---- mainloop ----
    for (int s = 0; s < NST; s++) {
        const int b = s & 1;
        const bool more = (s + 1 < NST);
        if (more) {
            a_ldg(s + 1);
            b_cpasync(s + 1, b ^ 1);
        }
        compute(b);
        if (more) a_sts(b ^ 1);
        asm volatile("cp.async.wait_group 0;" ::: "memory");
        __syncthreads();
    }

    // ---- epilogue: undo 2^16 scaling (exact) ----
    const float SC = 1.0f / 65536.0f;
#pragma unroll
    for (int m = 0; m < 2; m++) {
#pragma unroll
        for (int nt = 0; nt < 8; nt++) {
            const int row = bm + wm * 32 + m * 16 + (lane >> 2);
            const int col = bn + wn * 64 + nt * 8 + ((lane & 3) << 1);
            float* cp = C + (size_t)row * NEXP + col;
            *(float2*)cp = make_float2(acc[m][nt][0] * SC, acc[m][nt][1] * SC);
            *(float2*)(cp + 8 * NEXP) = make_float2(acc[m][nt][2] * SC, acc[m][nt][3] * SC);
        }
    }
}

// ======================== routing: one warp per token =======================
__global__ __launch_bounds__(256) void routing_kernel(
    const float* __restrict__ logits, const float* __restrict__ bias,
    float* __restrict__ out_idx, float* __restrict__ out_w, int T)
{
    const int wip  = threadIdx.x >> 5;
    const int lane = threadIdx.x & 31;
    const int t = blockIdx.x * 8 + wip;
    if (t >= T) return;

    __shared__ float s_sc[8][256];
    __shared__ float s_sr[8][256];
    __shared__ float s_gv[8][8];
    __shared__ int   s_gi[8][8];

    float* sc = s_sc[wip];
    float* sr = s_sr[wip];
    const float* lrow = logits + (size_t)t * 256;

#pragma unroll
    for (int i = 0; i < 8; i++) {
        int e = i * 32 + lane;
        float l = lrow[e];
        float s = 1.0f / (1.0f + expf(-l));
        sc[e] = s;
        sr[e] = s + bias[e];
    }
    __syncwarp();

    float gscore = -INFINITY;
    if (lane < 8) {
        float m1 = -INFINITY, m2 = -INFINITY;
#pragma unroll
        for (int j = 0; j < 32; j++) {
            float v = sr[lane * 32 + ((j + lane * 4) & 31)];
            if (v > m1) { m2 = m1; m1 = v; }
            else if (v > m2) { m2 = v; }
        }
        gscore = m1 + m2;
    }

    float gs[8];
#pragma unroll
    for (int g = 0; g < 8; g++) gs[g] = __shfl_sync(0xffffffffu, gscore, g);
    unsigned gmask = 0;
#pragma unroll
    for (int k = 0; k < 4; k++) {
        int bi = -1; float bv = -INFINITY;
#pragma unroll
        for (int g = 0; g < 8; g++) {
            bool taken = (gmask >> g) & 1u;
            if (!taken && gs[g] > bv) { bv = gs[g]; bi = g; }
        }
        gmask |= 1u << bi;
    }

    float vals[8];
#pragma unroll
    for (int i = 0; i < 8; i++)
        vals[i] = ((gmask >> i) & 1u) ? sr[i * 32 + lane] : -INFINITY;

    float sum = 0.0f;
    for (int k = 0; k < 8; k++) {
        float bv = -INFINITY; int bi = 0x7fffffff;
#pragma unroll
        for (int i = 0; i < 8; i++) {
            int e = i * 32 + lane;
            if (vals[i] > bv || (vals[i] == bv && e < bi)) { bv = vals[i]; bi = e; }
        }
#pragma unroll
        for (int off = 16; off; off >>= 1) {
            float ov = __shfl_xor_sync(0xffffffffu, bv, off);
            int   oi = __shfl_xor_sync(0xffffffffu, bi, off);
            if (ov > bv || (ov == bv && oi < bi)) { bv = ov; bi = oi; }
        }
        if ((bi & 31) == lane) vals[bi >> 5] = -INFINITY;
        float g = sc[bi];
        sum += g;
        if (lane == 0) { s_gv[wip][k] = g; s_gi[wip][k] = bi; }
    }
    __syncwarp();

    if (lane < 8) {
        float w = s_gv[wip][lane] / (sum + 1e-20f) * 2.5f;
        out_w[(size_t)t * 8 + lane]   = w;
        out_idx[(size_t)t * 8 + lane] = (float)s_gi[wip][lane];
    }
}

// ============================== launch ======================================
extern "C" void kernel_launch(void* const* d_in, const int* in_sizes, int n_in,
                              void* d_out, int out_size)
{
    const float* X    = (const float*)d_in[0];  // [T, H]
    const float* W    = (const float*)d_in[1];  // [E, H]
    const float* bias = (const float*)d_in[2];  // [E]

    const int E = in_sizes[2];
    const int H = in_sizes[1] / E;
    const int T = in_sizes[0] / H;

    float* out     = (float*)d_out;
    float* out_idx = out;
    float* out_w   = out + (size_t)T * 8;

    float* logits;
    if ((size_t)out_size >= (size_t)T * 16 + (size_t)T * E) {
        logits = out + (size_t)T * 16;
    } else {
        float* p;
        cudaGetSymbolAddress((void**)&p, g_logits_scratch);
        logits = p;
    }

    // 1) W -> two fp16 split arrays (scaled by 2^12)
    wsplit_kernel<<<(E * H / 4 + 255) / 256, 256>>>(W);

    // 2) tensor-core split GEMM -> logits (R9 shape, KC=64)
    cudaFuncSetAttribute(gemm_fp16_split,
                         cudaFuncAttributeMaxDynamicSharedMemorySize, GEMM_SMEM);
    dim3 grid(E / 128, T / 128);
    gemm_fp16_split<<<grid, 256, GEMM_SMEM>>>(X, logits);

    // 3) routing
    routing_kernel<<<(T + 7) / 8, 256>>>(logits, bias, out_idx, out_w, T);
}

// round 14
// speedup vs baseline: 1.6838x; 1.1987x over previous
#include <cuda_runtime.h>
#include <cuda_fp16.h>
#include <math.h>
#include <stdint.h>

// ---------------------------------------------------------------------------
// BailingMoeV2Gate (plain sm_103 target, no tcgen05):
// logits = X[T,4096] @ W[256,4096]^T via mma.sync.m16n8k16 fp16 2-way split,
// 3 products {x0w0, x0w1, x1w0}. W pre-scaled by 2^12, X by 2^4; epilogue
// x 2^-16. One 6-mma chain per 32-k stage (C=0 seeded) + Kahan RN master
// add -- accumulation order bit-identical to the R9 passing kernel.
// R13: 512 threads / 16 warps (4Mx4N, warp tile 32x32) -> per-thread state
// halves (acc32+cmp32), no spills, 4 warps/SMSP latency hiding.
// Output (fp32 concat): [T*8] idx, [T*8] weights, [T*256] logits.
// ---------------------------------------------------------------------------

#define HID   4096
#define NEXP  256
#define KC    32
#define NST   (HID / KC)   // 128 stages

__device__ float g_logits_scratch[16384 * 256];
__device__ __half g_W0[NEXP * HID];   // fp16(W * 4096)
__device__ __half g_W1[NEXP * HID];   // fp16 residual

__device__ __forceinline__ uint32_t smem_u32(const void* p) {
    uint32_t a;
    asm("{ .reg .u64 t; cvta.to.shared.u64 t, %1; cvt.u32.u64 %0, t; }"
        : "=r"(a) : "l"(p));
    return a;
}

#define MMA_INIT(d, a, b)                                                  \
    asm volatile(                                                          \
        "mma.sync.aligned.m16n8k16.row.col.f32.f16.f16.f32 "               \
        "{%0,%1,%2,%3}, {%4,%5,%6,%7}, {%8,%9}, {%10,%11,%12,%13};"        \
        : "=f"((d)[0]), "=f"((d)[1]), "=f"((d)[2]), "=f"((d)[3])           \
        : "r"((a)[0]), "r"((a)[1]), "r"((a)[2]), "r"((a)[3]),              \
          "r"((b)[0]), "r"((b)[1]),                                        \
          "f"(0.0f), "f"(0.0f), "f"(0.0f), "f"(0.0f))

#define MMA_ACC(d, a, b)                                                   \
    asm volatile(                                                          \
        "mma.sync.aligned.m16n8k16.row.col.f32.f16.f16.f32 "               \
        "{%0,%1,%2,%3}, {%4,%5,%6,%7}, {%8,%9}, {%0,%1,%2,%3};"            \
        : "+f"((d)[0]), "+f"((d)[1]), "+f"((d)[2]), "+f"((d)[3])           \
        : "r"((a)[0]), "r"((a)[1]), "r"((a)[2]), "r"((a)[3]),              \
          "r"((b)[0]), "r"((b)[1]))

#define LDMATRIX_X4(r, addr)                                               \
    asm volatile("ldmatrix.sync.aligned.m8n8.x4.shared.b16 "               \
                 "{%0,%1,%2,%3}, [%4];"                                    \
                 : "=r"((r)[0]), "=r"((r)[1]), "=r"((r)[2]), "=r"((r)[3])  \
                 : "r"(addr))

#define LDMATRIX_X2(r, addr)                                               \
    asm volatile("ldmatrix.sync.aligned.m8n8.x2.shared.b16 {%0,%1}, [%2];" \
                 : "=r"((r)[0]), "=r"((r)[1]) : "r"(addr))

#define CP_ASYNC16(dst, src)                                               \
    asm volatile("{ .reg .u64 g; cvta.to.global.u64 g, %1; "               \
                 "cp.async.ca.shared.global [%0], [g], 16; }"              \
                 :: "r"(dst), "l"(src))

// ====================== W split pre-kernel =================================
__global__ __launch_bounds__(256) void wsplit_kernel(const float* __restrict__ W) {
    size_t i = ((size_t)blockIdx.x * 256 + threadIdx.x) * 4;
    float4 v = *(const float4*)(W + i);
    float a[4] = {v.x, v.y, v.z, v.w};
#pragma unroll
    for (int j = 0; j < 4; j++) {
        float x = a[j] * 4096.0f;
        __half w0 = __float2half_rn(x);
        float r1 = x - __half2float(w0);
        __half w1 = __float2half_rn(r1);
        g_W0[i + j] = w0;
        g_W1[i + j] = w1;
    }
}

// ====================== split-fp16 mma.sync GEMM ===========================
// Grid (2, T/128): CTA tile M=128, N=128. 512 threads = 16 warps (4M x 4N),
// warp tile 32x32. KC=32 (2 k16 steps), 2-stage double buffer.
// SMEM fp16 tiles, 80B padded row stride (64B data + 16B pad).
#define A_ROW    80
#define A_SPLIT  (128 * A_ROW)       // 10240
#define A_BUF    (2 * A_SPLIT)       // 20480 (2 splits, one stage buffer)
#define B_OFF    (2 * A_BUF)         // 40960
#define B_SPLIT  (128 * A_ROW)
#define B_BUF    (2 * B_SPLIT)
#define GEMM_SMEM (B_OFF + 2 * B_BUF)  // 81920

__global__ void __launch_bounds__(512, 1) gemm_fp16_split(
    const float* __restrict__ X, float* __restrict__ C)
{
    extern __shared__ char smem[];
    const uint32_t sb = smem_u32(smem);
    const int tid  = threadIdx.x;
    const int lane = tid & 31;
    const int wid  = tid >> 5;
    const int wm   = wid >> 2;      // 0..3 (M)
    const int wn   = wid & 3;       // 0..3 (N)
    const int bm   = blockIdx.y * 128;
    const int bn   = blockIdx.x * 128;

    // ---- A loader: 512 threads, 8 floats each: row = tid>>2, q = tid&3 ----
    const int ar = tid >> 2;
    const int aq = tid & 3;
    const float* aptr = X + (size_t)(bm + ar) * HID + aq * 8;

    // ---- B loader: 2 cp.async 16B chunks per thread per stage ----
    // j = tid*2+c in [0,1024): p = j>>9, row = (j&511)>>2, ch = j&3
    const __half* wbase[2] = {g_W0, g_W1};

    float acc[2][4][4], cmp[2][4][4];
#pragma unroll
    for (int m = 0; m < 2; m++)
#pragma unroll
        for (int n = 0; n < 4; n++)
#pragma unroll
            for (int k = 0; k < 4; k++) { acc[m][n][k] = 0.0f; cmp[m][n][k] = 0.0f; }

    float4 xs0, xs1;   // 8 staged fp32

    auto a_ldg = [&](int s) {
        const float* p = aptr + s * KC;
        xs0 = *(const float4*)(p);
        xs1 = *(const float4*)(p + 4);
    };
    auto b_cpasync = [&](int s, int b) {
#pragma unroll
        for (int c = 0; c < 2; c++) {
            int j   = tid * 2 + c;
            int p   = j >> 9;
            int rem = j & 511;
            int row = rem >> 2;
            int ch  = rem & 3;
            const char* src = (const char*)(wbase[p] + (size_t)(bn + row) * HID + s * KC) + ch * 16;
            uint32_t dst = sb + B_OFF + b * B_BUF + p * B_SPLIT + row * A_ROW + ch * 16;
            CP_ASYNC16(dst, src);
        }
        asm volatile("cp.async.commit_group;" ::: "memory");
    };
    auto a_sts = [&](int b) {
        float xv[8] = {xs0.x, xs0.y, xs0.z, xs0.w, xs1.x, xs1.y, xs1.z, xs1.w};
        __half2 h0[4], h1[4];
#pragma unroll
        for (int i = 0; i < 4; i++) {
            float xa = xv[2 * i] * 16.0f;       // exact scale
            float xb = xv[2 * i + 1] * 16.0f;
            __half a0 = __float2half_rn(xa);
            float ra = xa - __half2float(a0);
            __half a1 = __float2half_rn(ra);
            __half b0 = __float2half_rn(xb);
            float rb = xb - __half2float(b0);
            __half b1 = __float2half_rn(rb);
            h0[i] = __half2(a0, b0);
            h1[i] = __half2(a1, b1);
        }
        char* base = smem + b * A_BUF + ar * A_ROW + aq * 16;
        *(uint4*)(base)           = *(const uint4*)h0;
        *(uint4*)(base + A_SPLIT) = *(const uint4*)h1;
    };

    // ---- ldmatrix addresses ----
    // A x4 (one m16 x k16 frag): mt = lane>>3: row (lane&7)+8*(mt&1), khalf mt>>1
    const int a_mt = lane >> 3;
    const uint32_t a_addr0 = sb + (wm * 32 + (lane & 7) + ((a_mt & 1) << 3)) * A_ROW
                           + (a_mt >> 1) * 16;
    // B x2: lanes 0-15: rows n = (l15&7), k-half = (l15>>3)*16
    const int l15 = lane & 15;
    const uint32_t b_addr0 = sb + B_OFF + (wn * 32 + (l15 & 7)) * A_ROW
                           + (l15 >> 3) * 16;

    auto compute = [&](int b) {
        uint32_t af[2][2][2][4];   // [split][m][kk][frag]
#pragma unroll
        for (int p = 0; p < 2; p++)
#pragma unroll
            for (int m = 0; m < 2; m++)
#pragma unroll
                for (int kk = 0; kk < 2; kk++)
                    LDMATRIX_X4(af[p][m][kk],
                        a_addr0 + b * A_BUF + p * A_SPLIT + m * 16 * A_ROW + kk * 32);
#pragma unroll
        for (int nt = 0; nt < 4; nt++) {
            uint32_t bf[2][2][2];  // [split][kk][frag]
#pragma unroll
            for (int p = 0; p < 2; p++)
#pragma unroll
                for (int kk = 0; kk < 2; kk++)
                    LDMATRIX_X2(bf[p][kk],
                        b_addr0 + b * B_BUF + p * B_SPLIT + nt * 8 * A_ROW + kk * 32);
#pragma unroll
            for (int m = 0; m < 2; m++) {
                float ch[4];       // one 6-mma chain per stage (C=0 seeded)
                MMA_INIT(ch, af[0][m][0], bf[0][0]);   // x0*w0 kk0
                MMA_ACC (ch, af[0][m][0], bf[1][0]);   // x0*w1 kk0
                MMA_ACC (ch, af[1][m][0], bf[0][0]);   // x1*w0 kk0
                MMA_ACC (ch, af[0][m][1], bf[0][1]);   // x0*w0 kk1
                MMA_ACC (ch, af[0][m][1], bf[1][1]);   // x0*w1 kk1
                MMA_ACC (ch, af[1][m][1], bf[0][1]);   // x1*w0 kk1
#pragma unroll
                for (int k = 0; k < 4; k++) {          // Kahan master add (RN)
                    float y = __fadd_rn(ch[k], -cmp[m][nt][k]);
                    float t = __fadd_rn(acc[m][nt][k], y);
                    cmp[m][nt][k] = __fadd_rn(__fadd_rn(t, -acc[m][nt][k]), -y);
                    acc[m][nt][k] = t;
                }
            }
        }
    };

    // ---- prologue ----
    a_ldg(0);
    b_cpasync(0, 0);
    a_sts(0);
    asm volatile("cp.async.wait_group 0;" ::: "memory");
    __syncthreads();

    // ---- mainloop ----
    for (int s = 0; s < NST; s++) {
        const int b = s & 1;
        const bool more = (s + 1 < NST);
        if (more) {
            a_ldg(s + 1);
            b_cpasync(s + 1, b ^ 1);
        }
        compute(b);
        if (more) a_sts(b ^ 1);
        asm volatile("cp.async.wait_group 0;" ::: "memory");
        __syncthreads();
    }

    // ---- epilogue: undo 2^16 scaling (exact) ----
    const float SC = 1.0f / 65536.0f;
#pragma unroll
    for (int m = 0; m < 2; m++) {
#pragma unroll
        for (int nt = 0; nt < 4; nt++) {
            const int row = bm + wm * 32 + m * 16 + (lane >> 2);
            const int col = bn + wn * 32 + nt * 8 + ((lane & 3) << 1);
            float* cp = C + (size_t)row * NEXP + col;
            *(float2*)cp = make_float2(acc[m][nt][0] * SC, acc[m][nt][1] * SC);
            *(float2*)(cp + 8 * NEXP) = make_float2(acc[m][nt][2] * SC, acc[m][nt][3] * SC);
        }
    }
}

// ======================== routing: one warp per token =======================
__global__ __launch_bounds__(256) void routing_kernel(
    const float* __restrict__ logits, const float* __restrict__ bias,
    float* __restrict__ out_idx, float* __restrict__ out_w, int T)
{
    const int wip  = threadIdx.x >> 5;
    const int lane = threadIdx.x & 31;
    const int t = blockIdx.x * 8 + wip;
    if (t >= T) return;

    __shared__ float s_sc[8][256];
    __shared__ float s_sr[8][256];
    __shared__ float s_gv[8][8];
    __shared__ int   s_gi[8][8];

    float* sc = s_sc[wip];
    float* sr = s_sr[wip];
    const float* lrow = logits + (size_t)t * 256;

#pragma unroll
    for (int i = 0; i < 8; i++) {
        int e = i * 32 + lane;
        float l = lrow[e];
        float s = 1.0f / (1.0f + expf(-l));
        sc[e] = s;
        sr[e] = s + bias[e];
    }
    __syncwarp();

    float gscore = -INFINITY;
    if (lane < 8) {
        float m1 = -INFINITY, m2 = -INFINITY;
#pragma unroll
        for (int j = 0; j < 32; j++) {
            float v = sr[lane * 32 + ((j + lane * 4) & 31)];
            if (v > m1) { m2 = m1; m1 = v; }
            else if (v > m2) { m2 = v; }
        }
        gscore = m1 + m2;
    }

    float gs[8];
#pragma unroll
    for (int g = 0; g < 8; g++) gs[g] = __shfl_sync(0xffffffffu, gscore, g);
    unsigned gmask = 0;
#pragma unroll
    for (int k = 0; k < 4; k++) {
        int bi = -1; float bv = -INFINITY;
#pragma unroll
        for (int g = 0; g < 8; g++) {
            bool taken = (gmask >> g) & 1u;
            if (!taken && gs[g] > bv) { bv = gs[g]; bi = g; }
        }
        gmask |= 1u << bi;
    }

    float vals[8];
#pragma unroll
    for (int i = 0; i < 8; i++)
        vals[i] = ((gmask >> i) & 1u) ? sr[i * 32 + lane] : -INFINITY;

    float sum = 0.0f;
    for (int k = 0; k < 8; k++) {
        float bv = -INFINITY; int bi = 0x7fffffff;
#pragma unroll
        for (int i = 0; i < 8; i++) {
            int e = i * 32 + lane;
            if (vals[i] > bv || (vals[i] == bv && e < bi)) { bv = vals[i]; bi = e; }
        }
#pragma unroll
        for (int off = 16; off; off >>= 1) {
            float ov = __shfl_xor_sync(0xffffffffu, bv, off);
            int   oi = __shfl_xor_sync(0xffffffffu, bi, off);
            if (ov > bv || (ov == bv && oi < bi)) { bv = ov; bi = oi; }
        }
        if ((bi & 31) == lane) vals[bi >> 5] = -INFINITY;
        float g = sc[bi];
        sum += g;
        if (lane == 0) { s_gv[wip][k] = g; s_gi[wip][k] = bi; }
    }
    __syncwarp();

    if (lane < 8) {
        float w = s_gv[wip][lane] / (sum + 1e-20f) * 2.5f;
        out_w[(size_t)t * 8 + lane]   = w;
        out_idx[(size_t)t * 8 + lane] = (float)s_gi[wip][lane];
    }
}

// ============================== launch ======================================
extern "C" void kernel_launch(void* const* d_in, const int* in_sizes, int n_in,
                              void* d_out, int out_size)
{
    const float* X    = (const float*)d_in[0];  // [T, H]
    const float* W    = (const float*)d_in[1];  // [E, H]
    const float* bias = (const float*)d_in[2];  // [E]

    const int E = in_sizes[2];
    const int H = in_sizes[1] / E;
    const int T = in_sizes[0] / H;

    float* out     = (float*)d_out;
    float* out_idx = out;
    float* out_w   = out + (size_t)T * 8;

    float* logits;
    if ((size_t)out_size >= (size_t)T * 16 + (size_t)T * E) {
        logits = out + (size_t)T * 16;
    } else {
        float* p;
        cudaGetSymbolAddress((void**)&p, g_logits_scratch);
        logits = p;
    }

    // 1) W -> two fp16 split arrays (scaled by 2^12)
    wsplit_kernel<<<(E * H / 4 + 255) / 256, 256>>>(W);

    // 2) tensor-core split GEMM -> logits (R9 tiles, 512 threads / 16 warps)
    cudaFuncSetAttribute(gemm_fp16_split,
                         cudaFuncAttributeMaxDynamicSharedMemorySize, GEMM_SMEM);
    dim3 grid(E / 128, T / 128);
    gemm_fp16_split<<<grid, 512, GEMM_SMEM>>>(X, logits);

    // 3) routing
    routing_kernel<<<(T + 7) / 8, 256>>>(logits, bias, out_idx, out_w, T);
}